// round 2
// baseline (speedup 1.0000x reference)
#include <cuda_runtime.h>
#include <cstdint>

#define B_   256
#define P_   196
#define ENC_ 2048
#define DEC_ 512
#define ATT_ 512
#define M_TOT (B_*P_)

// scratch (no cudaMalloc allowed)
__device__ float g_c[B_*ATT_];    // att2 + b_dec + b_enc
__device__ float g_att[M_TOT];    // pre-softmax logits (b_full dropped: softmax shift-invariant)

// ---------------------------------------------------------------------------
// Kernel 1: c[b,a] = decoder_hidden[b,:] @ W_dec[:,a] + b_dec[a] + b_enc[a]
// ---------------------------------------------------------------------------
__global__ void k_att2(const float* __restrict__ dec,
                       const float* __restrict__ W_dec,
                       const float* __restrict__ b_dec,
                       const float* __restrict__ b_enc) {
    const int BB = 4;
    int a  = threadIdx.x;            // 0..511
    int b0 = blockIdx.x * BB;
    __shared__ float sdec[BB][DEC_];
    for (int i = threadIdx.x; i < BB*DEC_; i += blockDim.x)
        sdec[i / DEC_][i % DEC_] = dec[b0*DEC_ + i];
    __syncthreads();
    float acc[BB] = {0.f, 0.f, 0.f, 0.f};
    for (int e = 0; e < DEC_; e++) {
        float w = W_dec[e*ATT_ + a];
#pragma unroll
        for (int bb = 0; bb < BB; bb++) acc[bb] += sdec[bb][e] * w;
    }
    float bias = b_dec[a] + b_enc[a];
#pragma unroll
    for (int bb = 0; bb < BB; bb++)
        g_c[(b0+bb)*ATT_ + a] = acc[bb] + bias;
}

// ---------------------------------------------------------------------------
// Kernel 2: fused logits GEMM
//   att[m] = sum_n relu( (enc @ W_enc)[m,n] + c[b(m),n] ) * W_full[n]
//   CTA tile: 64 (M) x 512 (full N), K in steps of 8, tf32 mma.sync, 4-stage
//   cp.async pipeline.
// ---------------------------------------------------------------------------
#define BM 64
#define BK 8
#define NK (ENC_/BK)     // 256 k-steps
#define NSTAGE 4
#define AS_STRIDE 12     // floats; (12*g + tg) % 32 conflict-free
#define BS_STRIDE 520    // floats; (8*tg + g) conflict-free
#define AS_ELEMS (BM*AS_STRIDE)          // 768
#define BS_ELEMS (BK*BS_STRIDE)          // 4160
// dynamic smem layout (floats)
#define OFF_AS   0
#define OFF_BS   (OFF_AS + NSTAGE*AS_ELEMS)             // 3072
#define OFF_CS   (OFF_BS + NSTAGE*BS_ELEMS)             // 3072+16640 = 19712
#define OFF_WS   (OFF_CS + 2*ATT_)                      // +1024 = 20736
#define OFF_SRED (OFF_WS + ATT_)                        // +512  = 21248
#define SMEM_FLOATS (OFF_SRED + BM*8)                   // +512  = 21760
#define SMEM_BYTES  (SMEM_FLOATS*4)                     // 87040

__device__ __forceinline__ uint32_t f2tf32(float f) {
    uint32_t r; asm volatile("cvt.rna.tf32.f32 %0, %1;" : "=r"(r) : "f"(f)); return r;
}
__device__ __forceinline__ void cp16(float* s, const float* g) {
    uint32_t sa = (uint32_t)__cvta_generic_to_shared(s);
    asm volatile("cp.async.cg.shared.global [%0], [%1], 16;" :: "r"(sa), "l"(g));
}
__device__ __forceinline__ void cp_commit() { asm volatile("cp.async.commit_group;"); }
__device__ __forceinline__ void cp_wait2()  { asm volatile("cp.async.wait_group 2;"); }

__global__ void __launch_bounds__(256, 1)
k_gemm(const float* __restrict__ enc,
       const float* __restrict__ W_enc,
       const float* __restrict__ W_full) {
    extern __shared__ __align__(16) float sm[];
    float* As   = sm + OFF_AS;
    float* Bs   = sm + OFF_BS;
    float* cs   = sm + OFF_CS;     // [2][ATT_]
    float* ws   = sm + OFF_WS;     // [ATT_]
    float* sred = sm + OFF_SRED;   // [BM][8]

    int tid = threadIdx.x;
    int m0  = blockIdx.x * BM;
    int bglob0 = m0 / P_;          // tile spans at most 2 batches (64 < 196)

    // epilogue constants
#pragma unroll
    for (int i = 0; i < 2; i++) ws[tid + i*256] = W_full[tid + i*256];
#pragma unroll
    for (int i = 0; i < 4; i++) {
        int idx = tid + i*256;
        int r = idx >> 9, c = idx & 511;
        int bb = bglob0 + r; if (bb > B_-1) bb = B_-1;
        cs[r*ATT_ + c] = g_c[bb*ATT_ + c];
    }

    auto load_stage = [&](int kt, int buf) {
        int k0 = kt * BK;
        float* a = As + buf*AS_ELEMS;
        float* b = Bs + buf*BS_ELEMS;
        if (tid < 128) {   // A: 64 rows x 8 k (two 16B chunks per row)
            int arow = tid >> 1, kg = (tid & 1) * 4;
            cp16(a + arow*AS_STRIDE + kg,
                 enc + (size_t)(m0 + arow)*ENC_ + k0 + kg);
        }
#pragma unroll
        for (int i = 0; i < 4; i++) {  // B: 8 rows x 512 n
            int idx = tid + i*256;
            int row = idx >> 7, col4 = idx & 127;
            cp16(b + row*BS_STRIDE + col4*4,
                 W_enc + (size_t)(k0 + row)*ATT_ + col4*4);
        }
    };

    float acc[4][8][4];
#pragma unroll
    for (int i = 0; i < 4; i++)
#pragma unroll
        for (int j = 0; j < 8; j++)
#pragma unroll
            for (int k = 0; k < 4; k++) acc[i][j][k] = 0.f;

    int warp = tid >> 5, lane = tid & 31;
    int g = lane >> 2, tg = lane & 3;
    int wn0 = warp * 64;   // each warp: all 64 rows x its 64 cols

    // prologue: stages 0..NSTAGE-2
#pragma unroll
    for (int s = 0; s < NSTAGE-1; s++) { load_stage(s, s); cp_commit(); }

    for (int kt = 0; kt < NK; kt++) {
        cp_wait2();          // all groups through stage kt complete (own)
        __syncthreads();     // visibility of other threads' copies + WAR guard
        if (kt + NSTAGE-1 < NK) load_stage(kt + NSTAGE-1, (kt + NSTAGE-1) & (NSTAGE-1));
        cp_commit();         // commit (possibly empty) to keep group counts uniform

        const float* a = As + (kt & (NSTAGE-1))*AS_ELEMS;
        const float* b = Bs + (kt & (NSTAGE-1))*BS_ELEMS;

        uint32_t af[4][4], bf[8][2];
#pragma unroll
        for (int ms = 0; ms < 4; ms++) {
            int r0 = ms*16 + g;
            af[ms][0] = f2tf32(a[ r0     *AS_STRIDE + tg    ]);
            af[ms][1] = f2tf32(a[(r0 + 8)*AS_STRIDE + tg    ]);
            af[ms][2] = f2tf32(a[ r0     *AS_STRIDE + tg + 4]);
            af[ms][3] = f2tf32(a[(r0 + 8)*AS_STRIDE + tg + 4]);
        }
#pragma unroll
        for (int ns = 0; ns < 8; ns++) {
            int c0 = wn0 + ns*8 + g;
            bf[ns][0] = f2tf32(b[ tg     *BS_STRIDE + c0]);
            bf[ns][1] = f2tf32(b[(tg + 4)*BS_STRIDE + c0]);
        }
#pragma unroll
        for (int ms = 0; ms < 4; ms++)
#pragma unroll
            for (int ns = 0; ns < 8; ns++)
                asm volatile(
                    "mma.sync.aligned.m16n8k8.row.col.f32.tf32.tf32.f32 "
                    "{%0,%1,%2,%3},{%4,%5,%6,%7},{%8,%9},{%0,%1,%2,%3};"
                    : "+f"(acc[ms][ns][0]), "+f"(acc[ms][ns][1]),
                      "+f"(acc[ms][ns][2]), "+f"(acc[ms][ns][3])
                    : "r"(af[ms][0]), "r"(af[ms][1]), "r"(af[ms][2]), "r"(af[ms][3]),
                      "r"(bf[ns][0]), "r"(bf[ns][1]));
    }

    // fused epilogue: +c, relu, *W_full, reduce over N
#pragma unroll
    for (int ms = 0; ms < 4; ms++) {
#pragma unroll
        for (int h = 0; h < 2; h++) {
            int row = ms*16 + h*8 + g;
            int m = m0 + row;
            int bsel = (m / P_) - bglob0;
            float s = 0.f;
#pragma unroll
            for (int ns = 0; ns < 8; ns++) {
#pragma unroll
                for (int j = 0; j < 2; j++) {
                    int col = wn0 + ns*8 + tg*2 + j;
                    float v = acc[ms][ns][h*2 + j] + cs[bsel*ATT_ + col];
                    s += fmaxf(v, 0.f) * ws[col];
                }
            }
            s += __shfl_xor_sync(0xffffffffu, s, 1);
            s += __shfl_xor_sync(0xffffffffu, s, 2);
            if (tg == 0) sred[row*8 + warp] = s;
        }
    }
    __syncthreads();
    if (tid < BM) {
        float s = 0.f;
#pragma unroll
        for (int w = 0; w < 8; w++) s += sred[tid*8 + w];
        g_att[m0 + tid] = s;
    }
}

// ---------------------------------------------------------------------------
// Kernel 3: softmax over P per batch
// ---------------------------------------------------------------------------
__global__ void k_softmax(float* __restrict__ alpha) {
    int b = blockIdx.x, t = threadIdx.x;
    __shared__ float sm[256];
    float x = (t < P_) ? g_att[b*P_ + t] : -1e30f;
    sm[t] = x; __syncthreads();
#pragma unroll
    for (int s = 128; s > 0; s >>= 1) {
        if (t < s) sm[t] = fmaxf(sm[t], sm[t+s]);
        __syncthreads();
    }
    float mx = sm[0]; __syncthreads();
    float e = (t < P_) ? __expf(x - mx) : 0.f;
    sm[t] = e; __syncthreads();
#pragma unroll
    for (int s = 128; s > 0; s >>= 1) {
        if (t < s) sm[t] += sm[t+s];
        __syncthreads();
    }
    float inv = 1.f / sm[0];
    if (t < P_) alpha[b*P_ + t] = e * inv;
}

// ---------------------------------------------------------------------------
// Kernel 4: context[b,e] = sum_p alpha[b,p] * enc[b,p,e]   (bandwidth bound)
// ---------------------------------------------------------------------------
__global__ void k_context(const float* __restrict__ enc,
                          const float* __restrict__ alpha,
                          float* __restrict__ ctx) {
    int b  = blockIdx.y;
    int e0 = blockIdx.x * 1024 + threadIdx.x * 4;
    __shared__ float sal[P_];
    if (threadIdx.x < P_) sal[threadIdx.x] = alpha[b*P_ + threadIdx.x];
    __syncthreads();
    const float4* base = (const float4*)(enc + (size_t)b * P_ * ENC_ + e0);
    float4 acc = make_float4(0.f, 0.f, 0.f, 0.f);
#pragma unroll 4
    for (int p = 0; p < P_; p++) {
        float a = sal[p];
        float4 v = base[p * (ENC_/4)];
        acc.x += a*v.x; acc.y += a*v.y; acc.z += a*v.z; acc.w += a*v.w;
    }
    *(float4*)(ctx + (size_t)b*ENC_ + e0) = acc;
}

// ---------------------------------------------------------------------------
extern "C" void kernel_launch(void* const* d_in, const int* in_sizes, int n_in,
                              void* d_out, int out_size) {
    const float* enc    = (const float*)d_in[0];
    const float* dec    = (const float*)d_in[1];
    const float* W_enc  = (const float*)d_in[2];
    const float* b_enc  = (const float*)d_in[3];
    const float* W_dec  = (const float*)d_in[4];
    const float* b_dec  = (const float*)d_in[5];
    const float* W_full = (const float*)d_in[6];
    // d_in[7] = b_full: softmax shift-invariant, att not an output -> unused
    (void)in_sizes; (void)n_in; (void)out_size;

    float* out   = (float*)d_out;
    float* ctx   = out;               // [B, ENC]
    float* alpha = out + B_*ENC_;     // [B, P]

    static int smem_set = 0;
    if (!smem_set) {
        cudaFuncSetAttribute(k_gemm, cudaFuncAttributeMaxDynamicSharedMemorySize, SMEM_BYTES);
        smem_set = 1;
    }

    k_att2   <<<B_/4, 512>>>(dec, W_dec, b_dec, b_enc);
    k_gemm   <<<M_TOT/BM, 256, SMEM_BYTES>>>(enc, W_enc, W_full);
    k_softmax<<<B_, 256>>>(alpha);
    k_context<<<dim3(ENC_/1024, B_), 256>>>(enc, alpha, ctx);
}

// round 4
// speedup vs baseline: 1.6408x; 1.6408x over previous
#include <cuda_runtime.h>
#include <cuda_fp16.h>
#include <cstdint>

#define B_   256
#define P_   196
#define ENC_ 2048
#define DEC_ 512
#define ATT_ 512
#define M_TOT (B_*P_)

// ---------------- scratch (__device__ globals; no cudaMalloc allowed) ------
__device__ float  g_c[B_*ATT_];          // att2 + b_dec + b_enc
__device__ float  g_att[M_TOT];          // pre-softmax logits (b_full dropped)
__device__ __half g_ench[(size_t)M_TOT*ENC_]; // fp16 copy of encoder_out (205 MB)
__device__ __half g_Wth[ATT_*ENC_];      // W_enc^T in fp16: [n][k] (2 MB)

// ---------------------------------------------------------------------------
__device__ __forceinline__ uint32_t smem_u32(const void* p) {
    uint32_t a;
    asm("{ .reg .u64 t; cvta.to.shared.u64 t, %1; cvt.u32.u64 %0, t; }" : "=r"(a) : "l"(p));
    return a;
}
__device__ __forceinline__ void cp16(uint32_t dst, const void* src) {
    asm volatile("cp.async.cg.shared.global [%0], [%1], 16;" :: "r"(dst), "l"(src));
}
#define CP_COMMIT() asm volatile("cp.async.commit_group;" ::: "memory")
#define CP_WAIT2()  asm volatile("cp.async.wait_group 2;" ::: "memory")

// ---------------------------------------------------------------------------
// Kernel 0a: convert encoder_out fp32 -> fp16
// ---------------------------------------------------------------------------
__global__ void k_convert(const float* __restrict__ enc) {
    size_t i = ((size_t)blockIdx.x * blockDim.x + threadIdx.x) * 8;
    float4 v0 = *(const float4*)(enc + i);
    float4 v1 = *(const float4*)(enc + i + 4);
    __half2 h[4];
    h[0] = __floats2half2_rn(v0.x, v0.y);
    h[1] = __floats2half2_rn(v0.z, v0.w);
    h[2] = __floats2half2_rn(v1.x, v1.y);
    h[3] = __floats2half2_rn(v1.z, v1.w);
    *(uint4*)(g_ench + i) = *(uint4*)h;
}

// ---------------------------------------------------------------------------
// Kernel 0b: transpose+convert W_enc [ENC,ATT] fp32 -> g_Wth [ATT][ENC] fp16
// ---------------------------------------------------------------------------
__global__ void k_transpose(const float* __restrict__ W) {
    __shared__ float t[32][33];
    int k0 = blockIdx.x * 32, n0 = blockIdx.y * 32;
    int x = threadIdx.x, y = threadIdx.y;   // 32 x 8
#pragma unroll
    for (int j = 0; j < 32; j += 8)
        t[y + j][x] = W[(size_t)(k0 + y + j) * ATT_ + n0 + x];
    __syncthreads();
#pragma unroll
    for (int j = 0; j < 32; j += 8)
        g_Wth[(size_t)(n0 + y + j) * ENC_ + k0 + x] = __float2half_rn(t[x][y + j]);
}

// ---------------------------------------------------------------------------
// Kernel 0c: zero logits accumulator
// ---------------------------------------------------------------------------
__global__ void k_zero() {
    int i = blockIdx.x * 1024 + threadIdx.x;
    if (i < M_TOT) g_att[i] = 0.f;
}

// ---------------------------------------------------------------------------
// Kernel 1: c[b,a] = dec[b,:] @ W_dec[:,a] + b_dec[a] + b_enc[a]
// ---------------------------------------------------------------------------
__global__ void k_att2(const float* __restrict__ dec,
                       const float* __restrict__ W_dec,
                       const float* __restrict__ b_dec,
                       const float* __restrict__ b_enc) {
    const int BB = 4;
    int a  = threadIdx.x;
    int b0 = blockIdx.x * BB;
    __shared__ float sdec[BB][DEC_];
    for (int i = threadIdx.x; i < BB*DEC_; i += blockDim.x)
        sdec[i / DEC_][i % DEC_] = dec[b0*DEC_ + i];
    __syncthreads();
    float acc[BB] = {0.f, 0.f, 0.f, 0.f};
    for (int e = 0; e < DEC_; e++) {
        float w = W_dec[e*ATT_ + a];
#pragma unroll
        for (int bb = 0; bb < BB; bb++) acc[bb] += sdec[bb][e] * w;
    }
    float bias = b_dec[a] + b_enc[a];
#pragma unroll
    for (int bb = 0; bb < BB; bb++)
        g_c[(b0+bb)*ATT_ + a] = acc[bb] + bias;
}

// ---------------------------------------------------------------------------
// Kernel 2: fp16 mma.sync fused logits GEMM
//   CTA tile 128(M) x 256(N), BK=32, 4-stage cp.async, warp tile 64x64.
//   partial att[m] = sum_n relu(D[m,n] + c[b,n]) * W_full[n]  -> atomicAdd
// ---------------------------------------------------------------------------
#define BM 128
#define BN 256
#define BK 32
#define NK (ENC_/BK)          // 64
#define NSTG 4
#define ROWB 80               // bytes per smem tile row (32 halves + 8 pad)
#define A_STG (BM*ROWB)       // 10240
#define B_STG (BN*ROWB)       // 20480
#define OFF_A    0
#define OFF_B    (NSTG*A_STG)                   // 40960
#define OFF_CS   (OFF_B + NSTG*B_STG)           // 122880
#define OFF_WS   (OFF_CS + 2*BN*4)              // 124928
#define OFF_SRED (OFF_WS + BN*4)                // 125952
#define SMEM_BYTES (OFF_SRED + BM*4*4)          // 128000

__device__ __forceinline__ void load_stage(uint32_t smb, int m0, int n0,
                                           int kt, int stg, int tid) {
    int k0 = kt * BK;
    // A: 128 rows x 4 chunks (16B = 8 halves each)
#pragma unroll
    for (int j = 0; j < 2; j++) {
        int i = tid + j*256;
        int row = i >> 2, c = i & 3;
        cp16(smb + OFF_A + stg*A_STG + row*ROWB + c*16,
             g_ench + (size_t)(m0 + row)*ENC_ + k0 + c*8);
    }
    // B: 256 rows x 4 chunks
#pragma unroll
    for (int j = 0; j < 4; j++) {
        int i = tid + j*256;
        int row = i >> 2, c = i & 3;
        cp16(smb + OFF_B + stg*B_STG + row*ROWB + c*16,
             g_Wth + (size_t)(n0 + row)*ENC_ + k0 + c*8);
    }
}

__global__ void __launch_bounds__(256, 1)
k_gemm(const float* __restrict__ W_full) {
    extern __shared__ __align__(16) char smem[];
    uint32_t smb = smem_u32(smem);
    float* cs   = (float*)(smem + OFF_CS);    // [2][BN]
    float* ws   = (float*)(smem + OFF_WS);    // [BN]
    float* sred = (float*)(smem + OFF_SRED);  // [BM][4]

    int tid = threadIdx.x;
    int wid = tid >> 5, lane = tid & 31;
    int g = lane >> 2, tg = lane & 3;
    int wm = wid >> 2, wn = wid & 3;          // warps: 2 (m) x 4 (n)
    int n0 = blockIdx.x * BN;                 // 0 or 256
    int m0 = blockIdx.y * BM;
    int bglob0 = m0 / P_;                     // tile spans <= 2 batches

    // epilogue constants (CTA's n-slice)
    ws[tid] = W_full[n0 + tid];
#pragma unroll
    for (int i = 0; i < 2; i++) {
        int bb = bglob0 + i; if (bb > B_-1) bb = B_-1;
        cs[i*BN + tid] = g_c[bb*ATT_ + n0 + tid];
    }

    float acc[4][8][4];
#pragma unroll
    for (int a = 0; a < 4; a++)
#pragma unroll
        for (int b = 0; b < 8; b++)
#pragma unroll
            for (int c = 0; c < 4; c++) acc[a][b][c] = 0.f;

    // prologue: stages 0..2
#pragma unroll
    for (int s = 0; s < NSTG-1; s++) { load_stage(smb, m0, n0, s, s, tid); CP_COMMIT(); }

#pragma unroll 1
    for (int kt = 0; kt < NK; kt++) {
        CP_WAIT2();          // stage kt landed (own view)
        __syncthreads();     // CTA visibility + WAR on reused buffer
        if (kt + NSTG-1 < NK) load_stage(smb, m0, n0, kt + NSTG-1, (kt + NSTG-1) & (NSTG-1), tid);
        CP_COMMIT();

        int stg = kt & (NSTG-1);
        const uint32_t* As = (const uint32_t*)(smem + OFF_A + stg*A_STG);  // row stride 20 u32
        const uint32_t* Bs = (const uint32_t*)(smem + OFF_B + stg*B_STG);

#pragma unroll
        for (int kk = 0; kk < 2; kk++) {      // two k16 steps
            int kb = kk * 8;                  // half2 offset within row
            uint32_t af[4][4], bf[8][2];
#pragma unroll
            for (int ms = 0; ms < 4; ms++) {
                int r = wm*64 + ms*16 + g;
                af[ms][0] = As[ r     *20 + kb + tg    ];
                af[ms][1] = As[(r + 8)*20 + kb + tg    ];
                af[ms][2] = As[ r     *20 + kb + tg + 4];
                af[ms][3] = As[(r + 8)*20 + kb + tg + 4];
            }
#pragma unroll
            for (int ns = 0; ns < 8; ns++) {
                int n = wn*64 + ns*8 + g;
                bf[ns][0] = Bs[n*20 + kb + tg    ];
                bf[ns][1] = Bs[n*20 + kb + tg + 4];
            }
#pragma unroll
            for (int ms = 0; ms < 4; ms++)
#pragma unroll
                for (int ns = 0; ns < 8; ns++)
                    asm volatile(
                        "mma.sync.aligned.m16n8k16.row.col.f32.f16.f16.f32 "
                        "{%0,%1,%2,%3},{%4,%5,%6,%7},{%8,%9},{%0,%1,%2,%3};"
                        : "+f"(acc[ms][ns][0]), "+f"(acc[ms][ns][1]),
                          "+f"(acc[ms][ns][2]), "+f"(acc[ms][ns][3])
                        : "r"(af[ms][0]), "r"(af[ms][1]), "r"(af[ms][2]), "r"(af[ms][3]),
                          "r"(bf[ns][0]), "r"(bf[ns][1]));
        }
    }

    // fused epilogue: +c, relu, *W_full, reduce over this CTA's 256 cols
#pragma unroll
    for (int ms = 0; ms < 4; ms++) {
#pragma unroll
        for (int h = 0; h < 2; h++) {
            int row = wm*64 + ms*16 + h*8 + g;
            int m = m0 + row;
            int bsel = (m / P_) - bglob0;
            const float* csr = cs + bsel*BN;
            float s = 0.f;
#pragma unroll
            for (int ns = 0; ns < 8; ns++) {
#pragma unroll
                for (int j = 0; j < 2; j++) {
                    int col = wn*64 + ns*8 + tg*2 + j;
                    float v = acc[ms][ns][h*2 + j] + csr[col];
                    s += fmaxf(v, 0.f) * ws[col];
                }
            }
            s += __shfl_xor_sync(0xffffffffu, s, 1);
            s += __shfl_xor_sync(0xffffffffu, s, 2);
            if (tg == 0) sred[row*4 + wn] = s;
        }
    }
    __syncthreads();
    if (tid < BM) {
        float s = 0.f;
#pragma unroll
        for (int w = 0; w < 4; w++) s += sred[tid*4 + w];
        atomicAdd(&g_att[m0 + tid], s);
    }
}

// ---------------------------------------------------------------------------
// Kernel 3: softmax over P per batch
// ---------------------------------------------------------------------------
__global__ void k_softmax(float* __restrict__ alpha) {
    int b = blockIdx.x, t = threadIdx.x;
    __shared__ float sm[256];
    float x = (t < P_) ? g_att[b*P_ + t] : -1e30f;
    sm[t] = x; __syncthreads();
#pragma unroll
    for (int s = 128; s > 0; s >>= 1) {
        if (t < s) sm[t] = fmaxf(sm[t], sm[t+s]);
        __syncthreads();
    }
    float mx = sm[0]; __syncthreads();
    float e = (t < P_) ? __expf(x - mx) : 0.f;
    sm[t] = e; __syncthreads();
#pragma unroll
    for (int s = 128; s > 0; s >>= 1) {
        if (t < s) sm[t] += sm[t+s];
        __syncthreads();
    }
    float inv = 1.f / sm[0];
    if (t < P_) alpha[b*P_ + t] = e * inv;
}

// ---------------------------------------------------------------------------
// Kernel 4: context from fp16 enc copy (205 MB instead of 411 MB)
// ---------------------------------------------------------------------------
__global__ void k_context(const float* __restrict__ alpha,
                          float* __restrict__ ctx) {
    int b  = blockIdx.x;
    int e0 = threadIdx.x * 8;     // 256 threads * 8 halves = 2048 = ENC_
    __shared__ float sal[P_];
    if (threadIdx.x < P_) sal[threadIdx.x] = alpha[b*P_ + threadIdx.x];
    __syncthreads();
    const __half* base = g_ench + (size_t)b * P_ * ENC_ + e0;
    float acc[8] = {0.f,0.f,0.f,0.f,0.f,0.f,0.f,0.f};
#pragma unroll 2
    for (int p = 0; p < P_; p++) {
        float a = sal[p];
        uint4 raw = *(const uint4*)(base + (size_t)p * ENC_);
        const __half2* h = (const __half2*)&raw;
#pragma unroll
        for (int q = 0; q < 4; q++) {
            float2 f = __half22float2(h[q]);
            acc[q*2]   += a * f.x;
            acc[q*2+1] += a * f.y;
        }
    }
    float4* o = (float4*)(ctx + (size_t)b*ENC_ + e0);
    o[0] = make_float4(acc[0], acc[1], acc[2], acc[3]);
    o[1] = make_float4(acc[4], acc[5], acc[6], acc[7]);
}

// ---------------------------------------------------------------------------
extern "C" void kernel_launch(void* const* d_in, const int* in_sizes, int n_in,
                              void* d_out, int out_size) {
    const float* enc    = (const float*)d_in[0];
    const float* dec    = (const float*)d_in[1];
    const float* W_enc  = (const float*)d_in[2];
    const float* b_enc  = (const float*)d_in[3];
    const float* W_dec  = (const float*)d_in[4];
    const float* b_dec  = (const float*)d_in[5];
    const float* W_full = (const float*)d_in[6];
    (void)in_sizes; (void)n_in; (void)out_size;

    float* out   = (float*)d_out;
    float* ctx   = out;               // [B, ENC]
    float* alpha = out + B_*ENC_;     // [B, P]

    static int smem_set = 0;
    if (!smem_set) {
        cudaFuncSetAttribute(k_gemm, cudaFuncAttributeMaxDynamicSharedMemorySize, SMEM_BYTES);
        smem_set = 1;
    }

    k_convert  <<<M_TOT*ENC_/(256*8), 256>>>(enc);
    k_transpose<<<dim3(ENC_/32, ATT_/32), dim3(32, 8)>>>(W_enc);
    k_zero     <<<(M_TOT + 1023)/1024, 1024>>>();
    k_att2     <<<B_/4, 512>>>(dec, W_dec, b_dec, b_enc);
    k_gemm     <<<dim3(ATT_/BN, M_TOT/BM), 256, SMEM_BYTES>>>(W_full);
    k_softmax  <<<B_, 256>>>(alpha);
    k_context  <<<B_, 256>>>(alpha, ctx);
}

// round 5
// speedup vs baseline: 1.9476x; 1.1870x over previous
#include <cuda_runtime.h>
#include <cuda_fp16.h>
#include <cstdint>

#define B_   256
#define P_   196
#define ENC_ 2048
#define DEC_ 512
#define ATT_ 512
#define M_TOT (B_*P_)

// ---------------- scratch (__device__ globals; no cudaMalloc allowed) ------
__device__ float  g_c[B_*ATT_];      // att2 + b_dec + b_enc  (atomic accum)
__device__ float  g_att[M_TOT];      // pre-softmax logits    (atomic accum)
__device__ __half g_Wth[ATT_*ENC_];  // W_enc^T fp16: [n][k] (2 MB)

// ---------------------------------------------------------------------------
__device__ __forceinline__ uint32_t smem_u32(const void* p) {
    uint32_t a;
    asm("{ .reg .u64 t; cvta.to.shared.u64 t, %1; cvt.u32.u64 %0, t; }" : "=r"(a) : "l"(p));
    return a;
}
__device__ __forceinline__ void cp16(uint32_t dst, const void* src) {
    asm volatile("cp.async.cg.shared.global [%0], [%1], 16;" :: "r"(dst), "l"(src));
}
#define CP_COMMIT() asm volatile("cp.async.commit_group;" ::: "memory")
#define CP_WAIT2()  asm volatile("cp.async.wait_group 2;" ::: "memory")

// ---------------------------------------------------------------------------
// Kernel 0: zero atomic accumulators
// ---------------------------------------------------------------------------
__global__ void k_zero() {
    int i = blockIdx.x * 1024 + threadIdx.x;
    if (i < M_TOT)   g_att[i] = 0.f;
    if (i < B_*ATT_) g_c[i]   = 0.f;
}

// ---------------------------------------------------------------------------
// Kernel 0b: transpose+convert W_enc [ENC,ATT] fp32 -> g_Wth [ATT][ENC] fp16
// ---------------------------------------------------------------------------
__global__ void k_transpose(const float* __restrict__ W) {
    __shared__ float t[32][33];
    int k0 = blockIdx.x * 32, n0 = blockIdx.y * 32;
    int x = threadIdx.x, y = threadIdx.y;   // 32 x 8
#pragma unroll
    for (int j = 0; j < 32; j += 8)
        t[y + j][x] = W[(size_t)(k0 + y + j) * ATT_ + n0 + x];
    __syncthreads();
#pragma unroll
    for (int j = 0; j < 32; j += 8)
        g_Wth[(size_t)(n0 + y + j) * ENC_ + k0 + x] = __float2half_rn(t[x][y + j]);
}

// ---------------------------------------------------------------------------
// Kernel 1: split-K att2: g_c[b,a] += dec[b,k0:k0+128] @ W_dec[k0:k0+128,a]
//   grid (64 batch-groups of 4, 4 k-splits); bias added by kz==0 block.
// ---------------------------------------------------------------------------
__global__ void k_att2(const float* __restrict__ dec,
                       const float* __restrict__ W_dec,
                       const float* __restrict__ b_dec,
                       const float* __restrict__ b_enc) {
    int b0 = blockIdx.x * 4;
    int kz = blockIdx.y;
    int k0 = kz * 128;
    int tid = threadIdx.x;            // 512
    __shared__ float sdec[4][128];
    {
        int bb = tid >> 7, e = tid & 127;
        sdec[bb][e] = dec[(b0 + bb)*DEC_ + k0 + e];
    }
    __syncthreads();
    int a = tid;
    float acc[4] = {0.f, 0.f, 0.f, 0.f};
#pragma unroll 4
    for (int e = 0; e < 128; e++) {
        float w = W_dec[(size_t)(k0 + e)*ATT_ + a];
#pragma unroll
        for (int bb = 0; bb < 4; bb++) acc[bb] += sdec[bb][e] * w;
    }
    float bias = (kz == 0) ? (b_dec[a] + b_enc[a]) : 0.f;
#pragma unroll
    for (int bb = 0; bb < 4; bb++)
        atomicAdd(&g_c[(b0+bb)*ATT_ + a], acc[bb] + bias);
}

// ---------------------------------------------------------------------------
// Kernel 2: fp16 mma.sync fused logits GEMM with in-kernel A conversion
//   CTA tile 64(M) x 256(N), BK=32, 4-stage pipeline:
//     B: cp.async fp16 from g_Wth.  A: LDG fp32 enc -> cvt -> STS fp16.
//   partial att[m] = sum_n relu(D[m,n] + c[b,n]) * W_full[n] -> atomicAdd
// ---------------------------------------------------------------------------
#define BM 64
#define BN 256
#define BK 32
#define NK (ENC_/BK)          // 64
#define NSTG 4
#define ROWB 80               // bytes per smem tile row (32 halves + 8 pad)
#define A_STG (BM*ROWB)       // 5120
#define B_STG (BN*ROWB)       // 20480
#define OFF_A    0
#define OFF_B    (NSTG*A_STG)                   // 20480
#define OFF_CS   (OFF_B + NSTG*B_STG)           // 102400
#define OFF_WS   (OFF_CS + 2*BN*4)              // 104448
#define OFF_SRED (OFF_WS + BN*4)                // 105472
#define SMEM_BYTES (OFF_SRED + BM*8*4)          // 107520

// A stage: thread (row=tid>>2, c=tid&3) loads 8 fp32, stores 16B fp16
__device__ __forceinline__ void a_ldg(const float* __restrict__ enc, int m0, int kt,
                                      int tid, float4& l0, float4& l1) {
    int row = tid >> 2, c = tid & 3;
    const float* src = enc + (size_t)(m0 + row)*ENC_ + kt*BK + c*8;
    l0 = *(const float4*)src;
    l1 = *(const float4*)(src + 4);
}
__device__ __forceinline__ void a_sts(char* smem, int stg, int tid,
                                      const float4& l0, const float4& l1) {
    int row = tid >> 2, c = tid & 3;
    __half2 h[4];
    h[0] = __floats2half2_rn(l0.x, l0.y);
    h[1] = __floats2half2_rn(l0.z, l0.w);
    h[2] = __floats2half2_rn(l1.x, l1.y);
    h[3] = __floats2half2_rn(l1.z, l1.w);
    *(uint4*)(smem + OFF_A + stg*A_STG + row*ROWB + c*16) = *(uint4*)h;
}
__device__ __forceinline__ void b_load(uint32_t smb, int n0, int kt, int stg, int tid) {
    int k0 = kt * BK;
#pragma unroll
    for (int j = 0; j < 4; j++) {
        int i = tid + j*256;
        int row = i >> 2, c = i & 3;
        cp16(smb + OFF_B + stg*B_STG + row*ROWB + c*16,
             g_Wth + (size_t)(n0 + row)*ENC_ + k0 + c*8);
    }
}

__global__ void __launch_bounds__(256, 2)
k_gemm(const float* __restrict__ enc, const float* __restrict__ W_full) {
    extern __shared__ __align__(16) char smem[];
    uint32_t smb = smem_u32(smem);
    float* cs   = (float*)(smem + OFF_CS);    // [2][BN]
    float* ws   = (float*)(smem + OFF_WS);    // [BN]
    float* sred = (float*)(smem + OFF_SRED);  // [BM][8]

    int tid = threadIdx.x;
    int wn = tid >> 5, lane = tid & 31;       // 8 warps across N
    int g = lane >> 2, tg = lane & 3;
    int n0 = blockIdx.x * BN;                 // 0 or 256
    int m0 = blockIdx.y * BM;
    int bglob0 = m0 / P_;                     // tile spans <= 2 batches

    // epilogue constants (CTA's n-slice)
    ws[tid] = W_full[n0 + tid];
#pragma unroll
    for (int i = 0; i < 2; i++) {
        int bb = bglob0 + i; if (bb > B_-1) bb = B_-1;
        cs[i*BN + tid] = g_c[bb*ATT_ + n0 + tid];
    }

    float acc[4][4][4];
#pragma unroll
    for (int a = 0; a < 4; a++)
#pragma unroll
        for (int b = 0; b < 4; b++)
#pragma unroll
            for (int c = 0; c < 4; c++) acc[a][b][c] = 0.f;

    // prologue: stages 0..2
#pragma unroll
    for (int s = 0; s < NSTG-1; s++) {
        float4 l0, l1;
        a_ldg(enc, m0, s, tid, l0, l1);
        a_sts(smem, s, tid, l0, l1);
        b_load(smb, n0, s, s, tid);
        CP_COMMIT();
    }

#pragma unroll 1
    for (int kt = 0; kt < NK; kt++) {
        CP_WAIT2();          // B stage kt landed (own view)
        __syncthreads();     // CTA visibility; all warps done with iter kt-1
        bool pre = (kt + NSTG-1 < NK);
        int stg3 = (kt + NSTG-1) & (NSTG-1);
        float4 l0, l1;
        if (pre) {
            a_ldg(enc, m0, kt + NSTG-1, tid, l0, l1);  // long-latency, used below
            b_load(smb, n0, kt + NSTG-1, stg3, tid);
        }
        CP_COMMIT();

        int stg = kt & (NSTG-1);
        const uint32_t* As = (const uint32_t*)(smem + OFF_A + stg*A_STG);  // stride 20 u32
        const uint32_t* Bs = (const uint32_t*)(smem + OFF_B + stg*B_STG);

#pragma unroll
        for (int kk = 0; kk < 2; kk++) {      // two k16 steps
            int kb = kk * 8;
            uint32_t af[4][4], bf[4][2];
#pragma unroll
            for (int ms = 0; ms < 4; ms++) {
                int r = ms*16 + g;
                af[ms][0] = As[ r     *20 + kb + tg    ];
                af[ms][1] = As[(r + 8)*20 + kb + tg    ];
                af[ms][2] = As[ r     *20 + kb + tg + 4];
                af[ms][3] = As[(r + 8)*20 + kb + tg + 4];
            }
#pragma unroll
            for (int ns = 0; ns < 4; ns++) {
                int n = wn*32 + ns*8 + g;
                bf[ns][0] = Bs[n*20 + kb + tg    ];
                bf[ns][1] = Bs[n*20 + kb + tg + 4];
            }
#pragma unroll
            for (int ms = 0; ms < 4; ms++)
#pragma unroll
                for (int ns = 0; ns < 4; ns++)
                    asm volatile(
                        "mma.sync.aligned.m16n8k16.row.col.f32.f16.f16.f32 "
                        "{%0,%1,%2,%3},{%4,%5,%6,%7},{%8,%9},{%0,%1,%2,%3};"
                        : "+f"(acc[ms][ns][0]), "+f"(acc[ms][ns][1]),
                          "+f"(acc[ms][ns][2]), "+f"(acc[ms][ns][3])
                        : "r"(af[ms][0]), "r"(af[ms][1]), "r"(af[ms][2]), "r"(af[ms][3]),
                          "r"(bf[ns][0]), "r"(bf[ns][1]));
            if (kk == 0 && pre) a_sts(smem, stg3, tid, l0, l1);  // LDG data ready by now
        }
    }

    // fused epilogue: +c, relu, *W_full, reduce over this CTA's 256 cols
#pragma unroll
    for (int ms = 0; ms < 4; ms++) {
#pragma unroll
        for (int h = 0; h < 2; h++) {
            int row = ms*16 + h*8 + g;
            int m = m0 + row;
            int bsel = (m / P_) - bglob0;
            const float* csr = cs + bsel*BN;
            float s = 0.f;
#pragma unroll
            for (int ns = 0; ns < 4; ns++) {
#pragma unroll
                for (int j = 0; j < 2; j++) {
                    int col = wn*32 + ns*8 + tg*2 + j;
                    float v = acc[ms][ns][h*2 + j] + csr[col];
                    s += fmaxf(v, 0.f) * ws[col];
                }
            }
            s += __shfl_xor_sync(0xffffffffu, s, 1);
            s += __shfl_xor_sync(0xffffffffu, s, 2);
            if (tg == 0) sred[row*8 + wn] = s;
        }
    }
    __syncthreads();
    if (tid < BM) {
        float s = 0.f;
#pragma unroll
        for (int w = 0; w < 8; w++) s += sred[tid*8 + w];
        atomicAdd(&g_att[m0 + tid], s);
    }
}

// ---------------------------------------------------------------------------
// Kernel 3: fused softmax (over P) + context GEMV (fp32 enc, HBM-bound)
//   grid (2 e-halves, B); both halves recompute softmax (cheap), half 0 writes alpha.
// ---------------------------------------------------------------------------
__global__ void k_softctx(const float* __restrict__ enc,
                          float* __restrict__ alpha,
                          float* __restrict__ ctx) {
    int b = blockIdx.y, t = threadIdx.x;
    __shared__ float sm[256];
    __shared__ float sal[P_];
    float x = (t < P_) ? g_att[b*P_ + t] : -1e30f;
    sm[t] = x; __syncthreads();
#pragma unroll
    for (int s = 128; s > 0; s >>= 1) {
        if (t < s) sm[t] = fmaxf(sm[t], sm[t+s]);
        __syncthreads();
    }
    float mx = sm[0]; __syncthreads();
    float e = (t < P_) ? __expf(x - mx) : 0.f;
    sm[t] = e; __syncthreads();
#pragma unroll
    for (int s = 128; s > 0; s >>= 1) {
        if (t < s) sm[t] += sm[t+s];
        __syncthreads();
    }
    float inv = 1.f / sm[0];
    float av = e * inv;
    if (t < P_) {
        sal[t] = av;
        if (blockIdx.x == 0) alpha[b*P_ + t] = av;
    }
    __syncthreads();

    int e0 = blockIdx.x * 1024 + t * 4;
    const float4* base = (const float4*)(enc + (size_t)b * P_ * ENC_ + e0);
    float4 acc = make_float4(0.f, 0.f, 0.f, 0.f);
#pragma unroll 4
    for (int p = 0; p < P_; p++) {
        float a = sal[p];
        float4 v = base[p * (ENC_/4)];
        acc.x += a*v.x; acc.y += a*v.y; acc.z += a*v.z; acc.w += a*v.w;
    }
    *(float4*)(ctx + (size_t)b*ENC_ + e0) = acc;
}

// ---------------------------------------------------------------------------
extern "C" void kernel_launch(void* const* d_in, const int* in_sizes, int n_in,
                              void* d_out, int out_size) {
    const float* enc    = (const float*)d_in[0];
    const float* dec    = (const float*)d_in[1];
    const float* W_enc  = (const float*)d_in[2];
    const float* b_enc  = (const float*)d_in[3];
    const float* W_dec  = (const float*)d_in[4];
    const float* b_dec  = (const float*)d_in[5];
    const float* W_full = (const float*)d_in[6];
    (void)in_sizes; (void)n_in; (void)out_size;

    float* out   = (float*)d_out;
    float* ctx   = out;               // [B, ENC]
    float* alpha = out + B_*ENC_;     // [B, P]

    static int smem_set = 0;
    if (!smem_set) {
        cudaFuncSetAttribute(k_gemm, cudaFuncAttributeMaxDynamicSharedMemorySize, SMEM_BYTES);
        smem_set = 1;
    }

    k_zero     <<<(B_*ATT_ + 1023)/1024, 1024>>>();
    k_transpose<<<dim3(ENC_/32, ATT_/32), dim3(32, 8)>>>(W_enc);
    k_att2     <<<dim3(B_/4, 4), 512>>>(dec, W_dec, b_dec, b_enc);
    k_gemm     <<<dim3(ATT_/BN, M_TOT/BM), 256, SMEM_BYTES>>>(enc, W_full);
    k_softctx  <<<dim3(2, B_), 256>>>(enc, alpha, ctx);
}